// round 7
// baseline (speedup 1.0000x reference)
#include <cuda_runtime.h>
#include <math.h>

typedef unsigned long long u64;

#define B_DIM 8
#define H_DIM 16
#define N_PTS 1024
#define ROWS  8          // rows per thread
#define GROUPS 128       // 128 groups * 8 rows = 1024 rows

__device__ float g_sde[B_DIM * H_DIM];

__device__ __forceinline__ u64 pk2(float lo, float hi) {
    u64 r; asm("mov.b64 %0, {%1,%2};" : "=l"(r) : "f"(lo), "f"(hi)); return r;
}
__device__ __forceinline__ u64 ffma2(u64 a, u64 b, u64 c) {
    u64 d; asm("fma.rn.f32x2 %0, %1, %2, %3;" : "=l"(d) : "l"(a), "l"(b), "l"(c)); return d;
}
__device__ __forceinline__ void unpk2(u64 v, float& lo, float& hi) {
    asm("mov.b64 {%0,%1}, %2;" : "=f"(lo), "=f"(hi) : "l"(v));
}

// One block per (b,h), 512 threads. g = t&127 owns rows 8g..8g+7;
// slice = t>>7 scans j-packs [slice*128, slice*128+128).
// sde = 2*mean_i min_j |refl_i - s_j|^2 (reflection isometry collapses both
// chamfer directions). Software-pipelined, packed-f32x2 inner loop.
__global__ void __launch_bounds__(512, 1)
chamfer_kernel(const float* __restrict__ y_pred, const float* __restrict__ sp)
{
    const int bh = blockIdx.x;
    const int b  = bh >> 4;
    const int t  = threadIdx.x;
    const int g  = t & (GROUPS - 1);
    const int slice = t >> 7;

    const float* yp = y_pred + 4 * bh;
    float nx = yp[0], ny = yp[1], nz = yp[2], pd = yp[3];
    float inv = 1.0f / sqrtf(nx * nx + ny * ny + nz * nz);
    nx *= inv; ny *= inv; nz *= inv;

    __shared__ ulonglong2 shA[513];   // {x0,x1, y0,y1} packed point pairs (+1 pad)
    __shared__ ulonglong2 shB[513];   // {z0,z1, ss0,ss1}
    __shared__ float red[GROUPS];

    const float* pb = sp + b * (N_PTS * 3);

    // ---- pack point table: thread t packs points 2t, 2t+1 ----
    {
        const float2* pb2 = (const float2*)pb;
        float2 q0 = pb2[3 * t + 0];
        float2 q1 = pb2[3 * t + 1];
        float2 q2 = pb2[3 * t + 2];
        float x0 = q0.x, y0 = q0.y, z0 = q1.x;
        float x1 = q1.y, y1 = q2.x, z1 = q2.y;
        float s0 = fmaf(x0, x0, fmaf(y0, y0, z0 * z0));
        float s1 = fmaf(x1, x1, fmaf(y1, y1, z1 * z1));
        float4 va; va.x = x0; va.y = x1; va.z = y0; va.w = y1;
        float4 vb; vb.x = z0; vb.y = z1; vb.z = s0; vb.w = s1;
        ((float4*)shA)[t] = va;
        ((float4*)shB)[t] = vb;
        if (t == 0) {                 // pad entry: prefetch target on last iter
            ((float4*)shA)[512] = va;
            ((float4*)shB)[512] = vb;
        }
    }

    // ---- reflect owned rows 8g..8g+7 ----
    u64 ax[ROWS], ay[ROWS], az[ROWS];
    float rr[ROWS];
    {
        const float* pr = pb + 3 * ROWS * g;
        #pragma unroll
        for (int i = 0; i < ROWS; ++i) {
            float sx = pr[3 * i + 0], sy = pr[3 * i + 1], sz = pr[3 * i + 2];
            float p = fmaf(nx, sx, fmaf(ny, sy, fmaf(nz, sz, pd)));
            float rx = fmaf(-2.0f * p, nx, sx);
            float ry = fmaf(-2.0f * p, ny, sy);
            float rz = fmaf(-2.0f * p, nz, sz);
            rr[i] = fmaf(rx, rx, fmaf(ry, ry, rz * rz));
            ax[i] = pk2(-2.0f * rx, -2.0f * rx);
            ay[i] = pk2(-2.0f * ry, -2.0f * ry);
            az[i] = pk2(-2.0f * rz, -2.0f * rz);
        }
    }

    __syncthreads();

    const float INF = __int_as_float(0x7f800000);
    float m0[ROWS], m1[ROWS];
    #pragma unroll
    for (int i = 0; i < ROWS; ++i) { m0[i] = INF; m1[i] = INF; }

    const int jbeg = slice << 7;

    // software-pipelined mainloop: prefetch pack jj+1 while computing jj
    ulonglong2 A  = shA[jbeg];
    ulonglong2 Bv = shB[jbeg];
    #pragma unroll 8
    for (int jj = 0; jj < 128; ++jj) {
        ulonglong2 An = shA[jbeg + jj + 1];
        ulonglong2 Bn = shB[jbeg + jj + 1];
        #pragma unroll
        for (int i = 0; i < ROWS; ++i) {
            u64 v = ffma2(az[i], Bv.x, Bv.y);
            v = ffma2(ay[i], A.y, v);
            v = ffma2(ax[i], A.x, v);
            float vl, vh; unpk2(v, vl, vh);
            m0[i] = fminf(m0[i], vl);
            m1[i] = fminf(m1[i], vh);
        }
        A = An; Bv = Bn;
    }

    __syncthreads();

    // slices 1..3 publish per-row partial mins into dead shA space
    float* pmin = (float*)shA;
    if (slice > 0) {
        float4* dst = (float4*)(pmin + ((slice - 1) * GROUPS + g) * ROWS);
        float4 a; a.x = fminf(m0[0], m1[0]); a.y = fminf(m0[1], m1[1]);
                  a.z = fminf(m0[2], m1[2]); a.w = fminf(m0[3], m1[3]);
        float4 c; c.x = fminf(m0[4], m1[4]); c.y = fminf(m0[5], m1[5]);
                  c.z = fminf(m0[6], m1[6]); c.w = fminf(m0[7], m1[7]);
        dst[0] = a; dst[1] = c;
    }
    __syncthreads();

    if (slice == 0) {
        const float4* p1 = (const float4*)(pmin + (0 * GROUPS + g) * ROWS);
        const float4* p2 = (const float4*)(pmin + (1 * GROUPS + g) * ROWS);
        const float4* p3 = (const float4*)(pmin + (2 * GROUPS + g) * ROWS);
        float4 a1 = p1[0], c1 = p1[1];
        float4 a2 = p2[0], c2 = p2[1];
        float4 a3 = p3[0], c3 = p3[1];
        float acc = 0.0f;
        acc += rr[0] + fminf(fminf(m0[0], m1[0]), fminf(a1.x, fminf(a2.x, a3.x)));
        acc += rr[1] + fminf(fminf(m0[1], m1[1]), fminf(a1.y, fminf(a2.y, a3.y)));
        acc += rr[2] + fminf(fminf(m0[2], m1[2]), fminf(a1.z, fminf(a2.z, a3.z)));
        acc += rr[3] + fminf(fminf(m0[3], m1[3]), fminf(a1.w, fminf(a2.w, a3.w)));
        acc += rr[4] + fminf(fminf(m0[4], m1[4]), fminf(c1.x, fminf(c2.x, c3.x)));
        acc += rr[5] + fminf(fminf(m0[5], m1[5]), fminf(c1.y, fminf(c2.y, c3.y)));
        acc += rr[6] + fminf(fminf(m0[6], m1[6]), fminf(c1.z, fminf(c2.z, c3.z)));
        acc += rr[7] + fminf(fminf(m0[7], m1[7]), fminf(c1.w, fminf(c2.w, c3.w)));
        red[g] = acc;
    }
    __syncthreads();

    if (t < 64) red[t] += red[t + 64];
    __syncthreads();
    if (t < 32) {
        float v = red[t] + red[t + 32];
        v += __shfl_down_sync(0xffffffffu, v, 16);
        v += __shfl_down_sync(0xffffffffu, v, 8);
        v += __shfl_down_sync(0xffffffffu, v, 4);
        v += __shfl_down_sync(0xffffffffu, v, 2);
        v += __shfl_down_sync(0xffffffffu, v, 1);
        if (t == 0) g_sde[bh] = 2.0f * (v * (1.0f / 1024.0f));
    }
}

// One block, 256 threads. ALL global loads issued up-front (full MLP),
// then exactly two barriers of serial depth. Thread t<128 = (b,h);
// warp w<8 also reduces batch w's centroid.
__global__ void __launch_bounds__(256, 1)
final_kernel(const float4* __restrict__ y_pred4, const float* __restrict__ sp,
             float* __restrict__ out)
{
    const int t = threadIdx.x;

    __shared__ float hnx[128], hny[128], hnz[128], hpd[128], hsd[128], hkey[128];
    __shared__ float cm[3][B_DIM];

    // ---- phase 0: issue ALL independent loads immediately ----
    float4 yv = make_float4(0.f, 0.f, 0.f, 0.f);
    float sde = 0.f;
    if (t < B_DIM * H_DIM) {
        yv  = y_pred4[t];         // one LDG.128 per head
        sde = g_sde[t];
    }

    // centroid: warp w = batch w; 24 LDG.128 per lane, all independent
    {
        const int w  = t >> 5;
        const int ln = t & 31;
        const float4* pb4 = (const float4*)(sp + w * (N_PTS * 3));
        float sx = 0.f, sy = 0.f, sz = 0.f;
        #pragma unroll
        for (int k = 0; k < 8; ++k) {
            int base = (ln * 8 + k) * 3;
            float4 f0 = pb4[base + 0];
            float4 f1 = pb4[base + 1];
            float4 f2 = pb4[base + 2];
            sx += f0.x + f0.w + f1.z + f2.y;
            sy += f0.y + f1.x + f1.w + f2.z;
            sz += f0.z + f1.y + f2.x + f2.w;
        }
        #pragma unroll
        for (int o = 16; o > 0; o >>= 1) {
            sx += __shfl_down_sync(0xffffffffu, sx, o);
            sy += __shfl_down_sync(0xffffffffu, sy, o);
            sz += __shfl_down_sync(0xffffffffu, sz, o);
        }
        if (ln == 0) {
            cm[0][w] = sx * (1.0f / N_PTS);
            cm[1][w] = sy * (1.0f / N_PTS);
            cm[2][w] = sz * (1.0f / N_PTS);
        }
    }

    // normalize + publish head state
    float nx = 0.f, ny = 0.f, nz = 0.f;
    if (t < B_DIM * H_DIM) {
        float iv = 1.0f / sqrtf(yv.x * yv.x + yv.y * yv.y + yv.z * yv.z);
        nx = yv.x * iv; ny = yv.y * iv; nz = yv.z * iv;
        hnx[t] = nx; hny[t] = ny; hnz[t] = nz; hpd[t] = yv.w; hsd[t] = sde;
    }
    __syncthreads();   // barrier 1

    const int eb = (t & 127) >> 4;
    const int eh = t & 15;
    const int base = eb * H_DIM;
    float conf = 0.f;
    bool keep = false;

    if (t < B_DIM * H_DIM) {
        float mn = hsd[base], mx = hsd[base];
        #pragma unroll
        for (int g2 = 1; g2 < H_DIM; ++g2) {
            mn = fminf(mn, hsd[base + g2]); mx = fmaxf(mx, hsd[base + g2]);
        }
        conf = 1.0f - (sde - mn) / fabsf(mx - mn);

        // (ang<30 || 180-ang<30)  <=>  |cos| > cos(30deg)  (acos monotone)
        const float COS30 = 0.86602540378443864676f;
        bool valid = (sde <= 10.0f);
        bool any = false;
        #pragma unroll
        for (int g2 = 0; g2 < H_DIM; ++g2) {
            if (g2 == eh) continue;
            float c = nx * hnx[base + g2] + ny * hny[base + g2] + nz * hnz[base + g2];
            c = fminf(1.0f, fmaxf(-1.0f, c));
            if (fabsf(c) > COS30 && (hsd[base + g2] <= 10.0f) && (sde >= hsd[base + g2]))
                any = true;
        }
        keep = valid && !any;
        hkey[t] = keep ? conf : __int_as_float(0xff800000);
    }
    __syncthreads();   // barrier 2

    if (t < B_DIM * H_DIM) {
        float key = hkey[t];
        int rank = 0;
        #pragma unroll
        for (int g2 = 0; g2 < H_DIM; ++g2) {
            float kg = hkey[base + g2];
            if (kg > key || (kg == key && g2 < eh)) rank++;
        }
        float* o = out + (base + rank) * 8;
        if (keep) {
            float cx = cm[0][eb], cy = cm[1][eb], cz = cm[2][eb];
            float pj = fmaf(nx, cx, fmaf(ny, cy, fmaf(nz, cz, hpd[t])));
            o[0] = nx; o[1] = ny; o[2] = nz;
            o[3] = cx - pj * nx;
            o[4] = cy - pj * ny;
            o[5] = cz - pj * nz;
            o[6] = conf;
            o[7] = sde;
        } else {
            #pragma unroll
            for (int c = 0; c < 8; ++c) o[c] = 0.0f;
        }
    }
}

extern "C" void kernel_launch(void* const* d_in, const int* in_sizes, int n_in,
                              void* d_out, int out_size)
{
    const float* y_pred = (const float*)d_in[0];   // (8,16,4)
    const float* sp     = (const float*)d_in[1];   // (8,1024,3)
    float* out          = (float*)d_out;           // (8,16,8)

    chamfer_kernel<<<B_DIM * H_DIM, 512>>>(y_pred, sp);
    final_kernel<<<1, 256>>>((const float4*)y_pred, sp, out);
}

// round 8
// speedup vs baseline: 1.1250x; 1.1250x over previous
#include <cuda_runtime.h>
#include <math.h>

typedef unsigned long long u64;

#define B_DIM 8
#define H_DIM 16
#define N_PTS 1024

__device__ float g_part[128][16];   // [ (b,itile) ][ head ] partial row-sums
__device__ float g_cm[B_DIM][3];

__device__ __forceinline__ u64 pk2(float lo, float hi) {
    u64 r; asm("mov.b64 %0, {%1,%2};" : "=l"(r) : "f"(lo), "f"(hi)); return r;
}
__device__ __forceinline__ u64 ffma2(u64 a, u64 b, u64 c) {
    u64 d; asm("fma.rn.f32x2 %0, %1, %2, %3;" : "=l"(d) : "l"(a), "l"(b), "l"(c)); return d;
}
__device__ __forceinline__ void unpk2(u64 v, float& lo, float& hi) {
    asm("mov.b64 {%0,%1}, %2;" : "=f"(lo), "=f"(hi) : "l"(v));
}

// Block = (batch, 64-row i-tile); 512 threads = 64 igroups x 2 headgroups x
// 4 j-slices. Key identity: |refl_i - s_j|^2 = |s_i - s_j|^2 + 4 p_i p_j
// with p = n.s + d, so the 3-FMA pair term |s_i-s_j|^2 is computed ONCE and
// amortized over 8 heads (one extra FFMA2 + mins per head).
// sde = 2*mean_i min_j d2 (reflection isometry collapses both directions).
__global__ void __launch_bounds__(512, 1)
chamfer_kernel(const float* __restrict__ y_pred, const float* __restrict__ sp)
{
    const int bh    = blockIdx.x;
    const int b     = bh >> 4;           // batch
    const int itile = bh & 15;           // 64-row tile
    const int t     = threadIdx.x;
    const int ig    = t & 63;            // row within tile
    const int hg    = (t >> 6) & 1;      // head group (heads hg*8 .. +7)
    const int js    = t >> 7;            // j slice (128 packs each)

    __shared__ ulonglong2 shA[512];      // {x0,x1, y0,y1} packed point pairs
    __shared__ ulonglong2 shB[512];      // {z0,z1, ss0,ss1}
    __shared__ u64  ptab[512 * 16];      // [jp*16 + h] : {p_h(2jp), p_h(2jp+1)}  (64KB)
    __shared__ float nh4[16][4];         // normalized plane (nx,ny,nz,d)
    __shared__ float wpart[4][8];
    __shared__ float ws[48];             // centroid warp partials

    const float* pb = sp + b * (N_PTS * 3);

    // ---- phase 1: pack point table (thread t packs points 2t,2t+1) ----
    {
        const float2* pb2 = (const float2*)pb;
        float2 q0 = pb2[3 * t + 0];
        float2 q1 = pb2[3 * t + 1];
        float2 q2 = pb2[3 * t + 2];
        float x0 = q0.x, y0 = q0.y, z0 = q1.x;
        float x1 = q1.y, y1 = q2.x, z1 = q2.y;
        float s0 = fmaf(x0, x0, fmaf(y0, y0, z0 * z0));
        float s1 = fmaf(x1, x1, fmaf(y1, y1, z1 * z1));
        float4 va; va.x = x0; va.y = x1; va.z = y0; va.w = y1;
        float4 vb; vb.x = z0; vb.y = z1; vb.z = s0; vb.w = s1;
        ((float4*)shA)[t] = va;
        ((float4*)shB)[t] = vb;

        // centroid partials (itile==0 blocks only) — proven R5 path
        if (itile == 0) {
            float cx = x0 + x1, cy = y0 + y1, cz = z0 + z1;
            #pragma unroll
            for (int o = 16; o > 0; o >>= 1) {
                cx += __shfl_down_sync(0xffffffffu, cx, o);
                cy += __shfl_down_sync(0xffffffffu, cy, o);
                cz += __shfl_down_sync(0xffffffffu, cz, o);
            }
            if ((t & 31) == 0) {
                int w = t >> 5;
                ws[w] = cx; ws[16 + w] = cy; ws[32 + w] = cz;
            }
        }
    }
    // normalized planes (warp 0, lanes 0..15)
    if (t < 16) {
        const float* yp = y_pred + 4 * (b * H_DIM + t);
        float nx = yp[0], ny = yp[1], nz = yp[2], pd = yp[3];
        float inv = 1.0f / sqrtf(nx * nx + ny * ny + nz * nz);
        nh4[t][0] = nx * inv; nh4[t][1] = ny * inv; nh4[t][2] = nz * inv; nh4[t][3] = pd;
    }
    __syncthreads();

    if (itile == 0 && t == 0) {
        float cx = 0, cy = 0, cz = 0;
        #pragma unroll
        for (int w = 0; w < 16; ++w) { cx += ws[w]; cy += ws[16 + w]; cz += ws[32 + w]; }
        g_cm[b][0] = cx * (1.0f / N_PTS);
        g_cm[b][1] = cy * (1.0f / N_PTS);
        g_cm[b][2] = cz * (1.0f / N_PTS);
    }

    // ---- phase 2: fill projection table ptab[jp][h] (packed over j) ----
    {
        const int hh = t >> 5;           // head 0..15
        const int ln = t & 31;
        u64 nxp = pk2(nh4[hh][0], nh4[hh][0]);
        u64 nyp = pk2(nh4[hh][1], nh4[hh][1]);
        u64 nzp = pk2(nh4[hh][2], nh4[hh][2]);
        u64 dp  = pk2(nh4[hh][3], nh4[hh][3]);
        #pragma unroll
        for (int rep = 0; rep < 16; ++rep) {
            int jp = ln + rep * 32;
            ulonglong2 A = shA[jp];
            ulonglong2 Bv = shB[jp];
            u64 p = ffma2(nzp, Bv.x, dp);
            p = ffma2(nyp, A.y, p);
            p = ffma2(nxp, A.x, p);
            ptab[jp * 16 + hh] = p;
        }
    }

    // ---- per-thread row constants: row i = itile*64 + ig ----
    const int row = itile * 64 + ig;
    float sx = pb[3 * row + 0], sy = pb[3 * row + 1], sz = pb[3 * row + 2];
    float ssi = fmaf(sx, sx, fmaf(sy, sy, sz * sz));
    u64 m2x = pk2(-2.0f * sx, -2.0f * sx);
    u64 m2y = pk2(-2.0f * sy, -2.0f * sy);
    u64 m2z = pk2(-2.0f * sz, -2.0f * sz);
    u64 p4[8];
    #pragma unroll
    for (int k = 0; k < 8; ++k) {
        int h = hg * 8 + k;
        float p = fmaf(nh4[h][0], sx, fmaf(nh4[h][1], sy, fmaf(nh4[h][2], sz, nh4[h][3])));
        p4[k] = pk2(4.0f * p, 4.0f * p);
    }
    __syncthreads();

    // ---- mainloop: 128 j-packs; D once, 8 heads amortized ----
    const float INF = __int_as_float(0x7f800000);
    float m0[8], m1[8];
    #pragma unroll
    for (int k = 0; k < 8; ++k) { m0[k] = INF; m1[k] = INF; }

    const int jbeg = js << 7;
    #pragma unroll 4
    for (int jj = 0; jj < 128; ++jj) {
        const int jp = jbeg + jj;
        ulonglong2 A  = shA[jp];
        ulonglong2 Bv = shB[jp];
        // v = ss_j - 2 s_i . s_j   (packed over 2 j's)
        u64 v = ffma2(m2z, Bv.x, Bv.y);
        v = ffma2(m2y, A.y, v);
        v = ffma2(m2x, A.x, v);
        const ulonglong2* pr = (const ulonglong2*)&ptab[jp * 16 + hg * 8];
        ulonglong2 q0 = pr[0], q1 = pr[1], q2 = pr[2], q3 = pr[3];
        {
            u64 d0 = ffma2(p4[0], q0.x, v); float l, h2; unpk2(d0, l, h2);
            m0[0] = fminf(m0[0], l); m1[0] = fminf(m1[0], h2);
            u64 d1 = ffma2(p4[1], q0.y, v); unpk2(d1, l, h2);
            m0[1] = fminf(m0[1], l); m1[1] = fminf(m1[1], h2);
            u64 d2 = ffma2(p4[2], q1.x, v); unpk2(d2, l, h2);
            m0[2] = fminf(m0[2], l); m1[2] = fminf(m1[2], h2);
            u64 d3 = ffma2(p4[3], q1.y, v); unpk2(d3, l, h2);
            m0[3] = fminf(m0[3], l); m1[3] = fminf(m1[3], h2);
            u64 d4 = ffma2(p4[4], q2.x, v); unpk2(d4, l, h2);
            m0[4] = fminf(m0[4], l); m1[4] = fminf(m1[4], h2);
            u64 d5 = ffma2(p4[5], q2.y, v); unpk2(d5, l, h2);
            m0[5] = fminf(m0[5], l); m1[5] = fminf(m1[5], h2);
            u64 d6 = ffma2(p4[6], q3.x, v); unpk2(d6, l, h2);
            m0[6] = fminf(m0[6], l); m1[6] = fminf(m1[6], h2);
            u64 d7 = ffma2(p4[7], q3.y, v); unpk2(d7, l, h2);
            m0[7] = fminf(m0[7], l); m1[7] = fminf(m1[7], h2);
        }
    }
    __syncthreads();

    // ---- reduce: cross-slice min, add ss_i, sum rows ----
    float* red = (float*)ptab;           // reuse dead ptab (needs 16KB)
    {
        const int idx = ((js * 64 + ig) * 2 + hg) * 8;
        #pragma unroll
        for (int k = 0; k < 8; ++k) red[idx + k] = fminf(m0[k], m1[k]);
    }
    __syncthreads();

    if (js == 0) {
        float val[8];
        #pragma unroll
        for (int k = 0; k < 8; ++k) {
            const int base = (ig * 2 + hg) * 8 + k;
            float m = red[base];
            m = fminf(m, red[base + 1024]);
            m = fminf(m, red[base + 2048]);
            m = fminf(m, red[base + 3072]);
            val[k] = ssi + m;
        }
        #pragma unroll
        for (int o = 16; o > 0; o >>= 1) {
            #pragma unroll
            for (int k = 0; k < 8; ++k)
                val[k] += __shfl_down_sync(0xffffffffu, val[k], o);
        }
        if ((t & 31) == 0) {
            const int w = t >> 5;        // w0:hg0/rows0-31 w1:hg0/rows32-63 w2:hg1.. w3:hg1..
            #pragma unroll
            for (int k = 0; k < 8; ++k) wpart[w][k] = val[k];
        }
    }
    __syncthreads();

    if (t < 16) {
        const int hgg = t >> 3, k = t & 7;
        g_part[bh][t] = wpart[hgg * 2 + 0][k] + wpart[hgg * 2 + 1][k];
    }
}

// One block, 128 threads (R5-proven structure): thread t = (b,h).
// sde assembled deterministically from the 16 i-tile partials.
__global__ void __launch_bounds__(128, 1)
final_kernel(const float* __restrict__ y_pred, float* __restrict__ out)
{
    const int t  = threadIdx.x;
    const int eb = t >> 4;
    const int eh = t & 15;

    __shared__ float hnx[128], hny[128], hnz[128], hsd[128], hkey[128];

    const float* ypp = y_pred + 4 * t;
    float nx = ypp[0], ny = ypp[1], nz = ypp[2], pd = ypp[3];
    float iv = 1.0f / sqrtf(nx * nx + ny * ny + nz * nz);
    nx *= iv; ny *= iv; nz *= iv;

    float acc = 0.0f;
    #pragma unroll
    for (int it = 0; it < 16; ++it) acc += g_part[eb * 16 + it][eh];
    float sde = 2.0f * (acc * (1.0f / 1024.0f));

    hnx[t] = nx; hny[t] = ny; hnz[t] = nz; hsd[t] = sde;
    __syncthreads();

    const int base = eb * H_DIM;
    float mn = hsd[base], mx = hsd[base];
    #pragma unroll
    for (int g2 = 1; g2 < H_DIM; ++g2) {
        mn = fminf(mn, hsd[base + g2]); mx = fmaxf(mx, hsd[base + g2]);
    }
    float conf = 1.0f - (sde - mn) / fabsf(mx - mn);

    // (ang<30 || 180-ang<30)  <=>  |cos| > cos(30deg)  (acos monotone)
    const float COS30 = 0.86602540378443864676f;
    bool valid = (sde <= 10.0f);
    bool any = false;
    #pragma unroll
    for (int g2 = 0; g2 < H_DIM; ++g2) {
        if (g2 == eh) continue;
        float c = nx * hnx[base + g2] + ny * hny[base + g2] + nz * hnz[base + g2];
        c = fminf(1.0f, fmaxf(-1.0f, c));
        if (fabsf(c) > COS30 && (hsd[base + g2] <= 10.0f) && (sde >= hsd[base + g2]))
            any = true;
    }
    bool keep = valid && !any;
    hkey[t] = keep ? conf : __int_as_float(0xff800000);
    __syncthreads();

    float key = hkey[t];
    int rank = 0;
    #pragma unroll
    for (int g2 = 0; g2 < H_DIM; ++g2) {
        float kg = hkey[base + g2];
        if (kg > key || (kg == key && g2 < eh)) rank++;
    }
    float* o = out + (base + rank) * 8;
    if (keep) {
        float cx = g_cm[eb][0], cy = g_cm[eb][1], cz = g_cm[eb][2];
        float pj = fmaf(nx, cx, fmaf(ny, cy, fmaf(nz, cz, pd)));
        o[0] = nx; o[1] = ny; o[2] = nz;
        o[3] = cx - pj * nx;
        o[4] = cy - pj * ny;
        o[5] = cz - pj * nz;
        o[6] = conf;
        o[7] = sde;
    } else {
        #pragma unroll
        for (int c = 0; c < 8; ++c) o[c] = 0.0f;
    }
}

extern "C" void kernel_launch(void* const* d_in, const int* in_sizes, int n_in,
                              void* d_out, int out_size)
{
    const float* y_pred = (const float*)d_in[0];   // (8,16,4)
    const float* sp     = (const float*)d_in[1];   // (8,1024,3)
    float* out          = (float*)d_out;           // (8,16,8)

    chamfer_kernel<<<B_DIM * H_DIM, 512>>>(y_pred, sp);
    final_kernel<<<1, 128>>>(y_pred, out);
}

// round 9
// speedup vs baseline: 1.1362x; 1.0100x over previous
#include <cuda_runtime.h>
#include <math.h>

typedef unsigned long long u64;

#define B_DIM 8
#define H_DIM 16
#define N_PTS 1024

__device__ float g_part[128][16];   // [ (b,itile) ][ head ] partial row-sums
__device__ float g_cm[B_DIM][3];

__device__ __forceinline__ u64 pk2(float lo, float hi) {
    u64 r; asm("mov.b64 %0, {%1,%2};" : "=l"(r) : "f"(lo), "f"(hi)); return r;
}
__device__ __forceinline__ u64 ffma2(u64 a, u64 b, u64 c) {
    u64 d; asm("fma.rn.f32x2 %0, %1, %2, %3;" : "=l"(d) : "l"(a), "l"(b), "l"(c)); return d;
}
__device__ __forceinline__ void unpk2(u64 v, float& lo, float& hi) {
    asm("mov.b64 {%0,%1}, %2;" : "=f"(lo), "=f"(hi) : "l"(v));
}

// Block = (batch, 64-row i-tile); 512 threads = 32 igroups x 2 headgroups x
// 8 j-slices; each thread owns TWO rows. Identity:
//   |refl_i - s_j|^2 = |s_i - s_j|^2 + 4 p_i p_j,  p = n.s + d
// so the pair term is computed once per row and the per-head correction is a
// single FFMA2; the 96B of LDS per j-pack now serves 32 pair-distances.
// sde = 2*mean_i min_j d2 (reflection isometry collapses both directions).
__global__ void __launch_bounds__(512, 1)
chamfer_kernel(const float* __restrict__ y_pred, const float* __restrict__ sp)
{
    const int bh    = blockIdx.x;
    const int b     = bh >> 4;           // batch
    const int itile = bh & 15;           // 64-row tile
    const int t     = threadIdx.x;
    const int ig    = t & 31;            // row-pair group (rows 2ig, 2ig+1)
    const int hg    = (t >> 5) & 1;      // head group (heads hg*8 .. +7)
    const int js    = t >> 6;            // j slice (64 packs each)

    __shared__ ulonglong2 shA[512];      // {x0,x1, y0,y1} packed point pairs
    __shared__ ulonglong2 shB[512];      // {z0,z1, ss0,ss1}
    __shared__ u64  ptab[512 * 16];      // [jp*16 + h] : {p_h(2jp), p_h(2jp+1)} (64KB)
    __shared__ float nh4[16][4];         // normalized plane (nx,ny,nz,d)
    __shared__ float ws[48];             // centroid warp partials

    const float* pb = sp + b * (N_PTS * 3);

    // ---- phase 1: pack point table (thread t packs points 2t,2t+1) ----
    {
        const float2* pb2 = (const float2*)pb;
        float2 q0 = pb2[3 * t + 0];
        float2 q1 = pb2[3 * t + 1];
        float2 q2 = pb2[3 * t + 2];
        float x0 = q0.x, y0 = q0.y, z0 = q1.x;
        float x1 = q1.y, y1 = q2.x, z1 = q2.y;
        float s0 = fmaf(x0, x0, fmaf(y0, y0, z0 * z0));
        float s1 = fmaf(x1, x1, fmaf(y1, y1, z1 * z1));
        float4 va; va.x = x0; va.y = x1; va.z = y0; va.w = y1;
        float4 vb; vb.x = z0; vb.y = z1; vb.z = s0; vb.w = s1;
        ((float4*)shA)[t] = va;
        ((float4*)shB)[t] = vb;

        // centroid partials (itile==0 blocks only) — proven path
        if (itile == 0) {
            float cx = x0 + x1, cy = y0 + y1, cz = z0 + z1;
            #pragma unroll
            for (int o = 16; o > 0; o >>= 1) {
                cx += __shfl_down_sync(0xffffffffu, cx, o);
                cy += __shfl_down_sync(0xffffffffu, cy, o);
                cz += __shfl_down_sync(0xffffffffu, cz, o);
            }
            if ((t & 31) == 0) {
                int w = t >> 5;
                ws[w] = cx; ws[16 + w] = cy; ws[32 + w] = cz;
            }
        }
    }
    // normalized planes (warp 0, lanes 0..15)
    if (t < 16) {
        const float* yp = y_pred + 4 * (b * H_DIM + t);
        float nx = yp[0], ny = yp[1], nz = yp[2], pd = yp[3];
        float inv = 1.0f / sqrtf(nx * nx + ny * ny + nz * nz);
        nh4[t][0] = nx * inv; nh4[t][1] = ny * inv; nh4[t][2] = nz * inv; nh4[t][3] = pd;
    }
    __syncthreads();

    if (itile == 0 && t == 0) {
        float cx = 0, cy = 0, cz = 0;
        #pragma unroll
        for (int w = 0; w < 16; ++w) { cx += ws[w]; cy += ws[16 + w]; cz += ws[32 + w]; }
        g_cm[b][0] = cx * (1.0f / N_PTS);
        g_cm[b][1] = cy * (1.0f / N_PTS);
        g_cm[b][2] = cz * (1.0f / N_PTS);
    }

    // ---- phase 2: fill projection table ptab[jp][h] (packed over j) ----
    {
        const int hh = t >> 5;           // head 0..15
        const int ln = t & 31;
        u64 nxp = pk2(nh4[hh][0], nh4[hh][0]);
        u64 nyp = pk2(nh4[hh][1], nh4[hh][1]);
        u64 nzp = pk2(nh4[hh][2], nh4[hh][2]);
        u64 dp  = pk2(nh4[hh][3], nh4[hh][3]);
        #pragma unroll
        for (int rep = 0; rep < 16; ++rep) {
            int jp = ln + rep * 32;
            ulonglong2 A = shA[jp];
            ulonglong2 Bv = shB[jp];
            u64 p = ffma2(nzp, Bv.x, dp);
            p = ffma2(nyp, A.y, p);
            p = ffma2(nxp, A.x, p);
            ptab[jp * 16 + hh] = p;
        }
    }

    // ---- per-thread row constants: rows 2ig, 2ig+1 of this i-tile ----
    const int r0 = itile * 64 + ig * 2;
    float sx0 = pb[3 * r0 + 0], sy0 = pb[3 * r0 + 1], sz0 = pb[3 * r0 + 2];
    float sx1 = pb[3 * r0 + 3], sy1 = pb[3 * r0 + 4], sz1 = pb[3 * r0 + 5];
    float ss0 = fmaf(sx0, sx0, fmaf(sy0, sy0, sz0 * sz0));
    float ss1 = fmaf(sx1, sx1, fmaf(sy1, sy1, sz1 * sz1));
    u64 m2x0 = pk2(-2.0f * sx0, -2.0f * sx0);
    u64 m2y0 = pk2(-2.0f * sy0, -2.0f * sy0);
    u64 m2z0 = pk2(-2.0f * sz0, -2.0f * sz0);
    u64 m2x1 = pk2(-2.0f * sx1, -2.0f * sx1);
    u64 m2y1 = pk2(-2.0f * sy1, -2.0f * sy1);
    u64 m2z1 = pk2(-2.0f * sz1, -2.0f * sz1);
    u64 p40[8], p41[8];
    #pragma unroll
    for (int k = 0; k < 8; ++k) {
        int h = hg * 8 + k;
        float pa = fmaf(nh4[h][0], sx0, fmaf(nh4[h][1], sy0, fmaf(nh4[h][2], sz0, nh4[h][3])));
        float pbv = fmaf(nh4[h][0], sx1, fmaf(nh4[h][1], sy1, fmaf(nh4[h][2], sz1, nh4[h][3])));
        p40[k] = pk2(4.0f * pa, 4.0f * pa);
        p41[k] = pk2(4.0f * pbv, 4.0f * pbv);
    }
    __syncthreads();

    // ---- mainloop: 64 j-packs; pair term once per row, 8 heads amortized ----
    const float INF = __int_as_float(0x7f800000);
    float m0[8], m1[8];
    #pragma unroll
    for (int k = 0; k < 8; ++k) { m0[k] = INF; m1[k] = INF; }

    const int jbeg = js << 6;
    #pragma unroll 4
    for (int jj = 0; jj < 64; ++jj) {
        const int jp = jbeg + jj;
        ulonglong2 A  = shA[jp];
        ulonglong2 Bv = shB[jp];
        // v_r = ss_j - 2 s_r . s_j   (packed over 2 j's), per row
        u64 v0 = ffma2(m2z0, Bv.x, Bv.y);
        v0 = ffma2(m2y0, A.y, v0);
        v0 = ffma2(m2x0, A.x, v0);
        u64 v1 = ffma2(m2z1, Bv.x, Bv.y);
        v1 = ffma2(m2y1, A.y, v1);
        v1 = ffma2(m2x1, A.x, v1);
        const ulonglong2* pr = (const ulonglong2*)&ptab[jp * 16 + hg * 8];
        ulonglong2 q0 = pr[0], q1 = pr[1], q2 = pr[2], q3 = pr[3];
        u64 qa[8];
        qa[0] = q0.x; qa[1] = q0.y; qa[2] = q1.x; qa[3] = q1.y;
        qa[4] = q2.x; qa[5] = q2.y; qa[6] = q3.x; qa[7] = q3.y;
        #pragma unroll
        for (int k = 0; k < 8; ++k) {
            float l, h;
            u64 d0 = ffma2(p40[k], qa[k], v0);
            unpk2(d0, l, h);
            m0[k] = fminf(m0[k], fminf(l, h));
            u64 d1 = ffma2(p41[k], qa[k], v1);
            unpk2(d1, l, h);
            m1[k] = fminf(m1[k], fminf(l, h));
        }
    }
    __syncthreads();

    // ---- reduce: store per-thread mins, min over slices, sum rows ----
    float* red = (float*)ptab;           // reuse dead ptab (needs 32KB of 64KB)
    {
        float4* d = (float4*)(red + (((js * 32 + ig) * 2 + hg) * 2) * 8);
        d[0] = make_float4(m0[0], m0[1], m0[2], m0[3]);
        d[1] = make_float4(m0[4], m0[5], m0[6], m0[7]);
        d[2] = make_float4(m1[0], m1[1], m1[2], m1[3]);
        d[3] = make_float4(m1[4], m1[5], m1[6], m1[7]);
    }
    __syncthreads();

    if (js == 0) {                        // t < 64: same (ig, hg) as mainloop
        const int base = ((ig * 2 + hg) * 2) * 8;
        const float4* p = (const float4*)(red + base);
        float4 A0 = p[0], A1 = p[1], B0 = p[2], B1 = p[3];
        #pragma unroll
        for (int s = 1; s < 8; ++s) {
            const float4* q = (const float4*)(red + base + s * 1024);
            float4 x0 = q[0], x1 = q[1], x2 = q[2], x3 = q[3];
            A0.x = fminf(A0.x, x0.x); A0.y = fminf(A0.y, x0.y);
            A0.z = fminf(A0.z, x0.z); A0.w = fminf(A0.w, x0.w);
            A1.x = fminf(A1.x, x1.x); A1.y = fminf(A1.y, x1.y);
            A1.z = fminf(A1.z, x1.z); A1.w = fminf(A1.w, x1.w);
            B0.x = fminf(B0.x, x2.x); B0.y = fminf(B0.y, x2.y);
            B0.z = fminf(B0.z, x2.z); B0.w = fminf(B0.w, x2.w);
            B1.x = fminf(B1.x, x3.x); B1.y = fminf(B1.y, x3.y);
            B1.z = fminf(B1.z, x3.z); B1.w = fminf(B1.w, x3.w);
        }
        float val[8];
        val[0] = (ss0 + A0.x) + (ss1 + B0.x);
        val[1] = (ss0 + A0.y) + (ss1 + B0.y);
        val[2] = (ss0 + A0.z) + (ss1 + B0.z);
        val[3] = (ss0 + A0.w) + (ss1 + B0.w);
        val[4] = (ss0 + A1.x) + (ss1 + B1.x);
        val[5] = (ss0 + A1.y) + (ss1 + B1.y);
        val[6] = (ss0 + A1.z) + (ss1 + B1.z);
        val[7] = (ss0 + A1.w) + (ss1 + B1.w);
        #pragma unroll
        for (int o = 16; o > 0; o >>= 1) {
            #pragma unroll
            for (int k = 0; k < 8; ++k)
                val[k] += __shfl_down_sync(0xffffffffu, val[k], o);
        }
        if (ig == 0) {                   // lane 0 of warp hg
            #pragma unroll
            for (int k = 0; k < 8; ++k)
                g_part[bh][hg * 8 + k] = val[k];
        }
    }
}

// One block, 128 threads (proven structure): thread t = (b,h).
// sde assembled deterministically from the 16 i-tile partials.
__global__ void __launch_bounds__(128, 1)
final_kernel(const float* __restrict__ y_pred, float* __restrict__ out)
{
    const int t  = threadIdx.x;
    const int eb = t >> 4;
    const int eh = t & 15;

    __shared__ float hnx[128], hny[128], hnz[128], hsd[128], hkey[128];

    const float* ypp = y_pred + 4 * t;
    float nx = ypp[0], ny = ypp[1], nz = ypp[2], pd = ypp[3];
    float iv = 1.0f / sqrtf(nx * nx + ny * ny + nz * nz);
    nx *= iv; ny *= iv; nz *= iv;

    float acc = 0.0f;
    #pragma unroll
    for (int it = 0; it < 16; ++it) acc += g_part[eb * 16 + it][eh];
    float sde = 2.0f * (acc * (1.0f / 1024.0f));

    hnx[t] = nx; hny[t] = ny; hnz[t] = nz; hsd[t] = sde;
    __syncthreads();

    const int base = eb * H_DIM;
    float mn = hsd[base], mx = hsd[base];
    #pragma unroll
    for (int g2 = 1; g2 < H_DIM; ++g2) {
        mn = fminf(mn, hsd[base + g2]); mx = fmaxf(mx, hsd[base + g2]);
    }
    float conf = 1.0f - (sde - mn) / fabsf(mx - mn);

    // (ang<30 || 180-ang<30)  <=>  |cos| > cos(30deg)  (acos monotone)
    const float COS30 = 0.86602540378443864676f;
    bool valid = (sde <= 10.0f);
    bool any = false;
    #pragma unroll
    for (int g2 = 0; g2 < H_DIM; ++g2) {
        if (g2 == eh) continue;
        float c = nx * hnx[base + g2] + ny * hny[base + g2] + nz * hnz[base + g2];
        c = fminf(1.0f, fmaxf(-1.0f, c));
        if (fabsf(c) > COS30 && (hsd[base + g2] <= 10.0f) && (sde >= hsd[base + g2]))
            any = true;
    }
    bool keep = valid && !any;
    hkey[t] = keep ? conf : __int_as_float(0xff800000);
    __syncthreads();

    float key = hkey[t];
    int rank = 0;
    #pragma unroll
    for (int g2 = 0; g2 < H_DIM; ++g2) {
        float kg = hkey[base + g2];
        if (kg > key || (kg == key && g2 < eh)) rank++;
    }
    float* o = out + (base + rank) * 8;
    if (keep) {
        float cx = g_cm[eb][0], cy = g_cm[eb][1], cz = g_cm[eb][2];
        float pj = fmaf(nx, cx, fmaf(ny, cy, fmaf(nz, cz, pd)));
        o[0] = nx; o[1] = ny; o[2] = nz;
        o[3] = cx - pj * nx;
        o[4] = cy - pj * ny;
        o[5] = cz - pj * nz;
        o[6] = conf;
        o[7] = sde;
    } else {
        #pragma unroll
        for (int c = 0; c < 8; ++c) o[c] = 0.0f;
    }
}

extern "C" void kernel_launch(void* const* d_in, const int* in_sizes, int n_in,
                              void* d_out, int out_size)
{
    const float* y_pred = (const float*)d_in[0];   // (8,16,4)
    const float* sp     = (const float*)d_in[1];   // (8,1024,3)
    float* out          = (float*)d_out;           // (8,16,8)

    chamfer_kernel<<<B_DIM * H_DIM, 512>>>(y_pred, sp);
    final_kernel<<<1, 128>>>(y_pred, out);
}

// round 11
// speedup vs baseline: 1.2302x; 1.0827x over previous
#include <cuda_runtime.h>
#include <math.h>

typedef unsigned long long u64;

#define B_DIM 8
#define H_DIM 16
#define N_PTS 1024

__device__ float g_part[128][16];   // [ (b,itile) ][ head ] partial row-sums
__device__ float g_cm[B_DIM][3];

__device__ __forceinline__ u64 pk2(float lo, float hi) {
    u64 r; asm("mov.b64 %0, {%1,%2};" : "=l"(r) : "f"(lo), "f"(hi)); return r;
}
__device__ __forceinline__ u64 ffma2(u64 a, u64 b, u64 c) {
    u64 d; asm("fma.rn.f32x2 %0, %1, %2, %3;" : "=l"(d) : "l"(a), "l"(b), "l"(c)); return d;
}
__device__ __forceinline__ void unpk2(u64 v, float& lo, float& hi) {
    asm("mov.b64 {%0,%1}, %2;" : "=f"(lo), "=f"(hi) : "l"(v));
}

// Block = (batch, 64-row i-tile); 256 threads = 16 igroups (4 rows each)
// x 2 headgroups (8 heads) x 8 j-slices (64 packs each).
// Identity: |refl_i - s_j|^2 = |s_i - s_j|^2 + 4 p_i p_j,  p = n.s + d.
// Each j-pack's 96B of broadcast LDS now serves 64 pair-distances
// (4 rows x 8 heads x 2 j), pushing LDS below the 1-FMNMX-per-pair alu
// floor. 256 threads => 255-reg cap, which is what makes R=4 fit.
// sde = 2*mean_i min_j d2 (reflection isometry collapses both directions).
__global__ void __launch_bounds__(256)
chamfer_kernel(const float* __restrict__ y_pred, const float* __restrict__ sp)
{
    const int bh    = blockIdx.x;
    const int b     = bh >> 4;           // batch
    const int itile = bh & 15;           // 64-row tile
    const int t     = threadIdx.x;
    const int ig    = t & 15;            // row group (rows 4ig..4ig+3)
    const int hg    = (t >> 4) & 1;      // head group (heads hg*8..+7)
    const int js    = t >> 5;            // j slice (64 packs)

    __shared__ ulonglong2 shA[513];      // {x0,x1, y0,y1} packed point pairs (+pad)
    __shared__ ulonglong2 shB[513];      // {z0,z1, ss0,ss1}
    __shared__ u64  ptab[513 * 16];      // [jp*16 + h] : {p_h(2jp), p_h(2jp+1)}
    __shared__ float nh4[16][4];         // normalized plane (nx,ny,nz,d)
    __shared__ float ssv[64];            // ss per row of this i-tile
    __shared__ float ws[24];             // centroid warp partials

    const float* pb = sp + b * (N_PTS * 3);

    // ---- phase 1: pack point table (2 chunks of 256 threads) ----
    {
        float cx = 0.f, cy = 0.f, cz = 0.f;
        #pragma unroll
        for (int c = 0; c < 2; ++c) {
            const int tt = t + c * 256;
            const float2* pb2 = (const float2*)pb;
            float2 q0 = pb2[3 * tt + 0];
            float2 q1 = pb2[3 * tt + 1];
            float2 q2 = pb2[3 * tt + 2];
            float x0 = q0.x, y0 = q0.y, z0 = q1.x;
            float x1 = q1.y, y1 = q2.x, z1 = q2.y;
            float s0 = fmaf(x0, x0, fmaf(y0, y0, z0 * z0));
            float s1 = fmaf(x1, x1, fmaf(y1, y1, z1 * z1));
            float4 va; va.x = x0; va.y = x1; va.z = y0; va.w = y1;
            float4 vb; vb.x = z0; vb.y = z1; vb.z = s0; vb.w = s1;
            ((float4*)shA)[tt] = va;
            ((float4*)shB)[tt] = vb;
            if (tt == 0) {               // pad (prefetch target only, never computed)
                ((float4*)shA)[512] = va;
                ((float4*)shB)[512] = vb;
            }
            cx += x0 + x1; cy += y0 + y1; cz += z0 + z1;
        }
        if (itile == 0) {
            #pragma unroll
            for (int o = 16; o > 0; o >>= 1) {
                cx += __shfl_down_sync(0xffffffffu, cx, o);
                cy += __shfl_down_sync(0xffffffffu, cy, o);
                cz += __shfl_down_sync(0xffffffffu, cz, o);
            }
            if ((t & 31) == 0) {
                int w = t >> 5;
                ws[w] = cx; ws[8 + w] = cy; ws[16 + w] = cz;
            }
        }
    }
    // normalized planes (warp 0, lanes 0..15)
    if (t < 16) {
        const float* yp = y_pred + 4 * (b * H_DIM + t);
        float nx = yp[0], ny = yp[1], nz = yp[2], pd = yp[3];
        float inv = 1.0f / sqrtf(nx * nx + ny * ny + nz * nz);
        nh4[t][0] = nx * inv; nh4[t][1] = ny * inv; nh4[t][2] = nz * inv; nh4[t][3] = pd;
    }
    __syncthreads();

    if (itile == 0 && t == 0) {
        float cx = 0, cy = 0, cz = 0;
        #pragma unroll
        for (int w = 0; w < 8; ++w) { cx += ws[w]; cy += ws[8 + w]; cz += ws[16 + w]; }
        g_cm[b][0] = cx * (1.0f / N_PTS);
        g_cm[b][1] = cy * (1.0f / N_PTS);
        g_cm[b][2] = cz * (1.0f / N_PTS);
    }

    // ---- phase 2: fill projection table ptab[jp][h] (2 heads/thread) ----
    {
        const int ln = t & 31;
        #pragma unroll
        for (int hc = 0; hc < 2; ++hc) {
            const int hh = (t >> 5) + hc * 8;    // head 0..15
            u64 nxp = pk2(nh4[hh][0], nh4[hh][0]);
            u64 nyp = pk2(nh4[hh][1], nh4[hh][1]);
            u64 nzp = pk2(nh4[hh][2], nh4[hh][2]);
            u64 dp  = pk2(nh4[hh][3], nh4[hh][3]);
            #pragma unroll
            for (int rep = 0; rep < 16; ++rep) {
                int jp = ln + rep * 32;
                ulonglong2 A = shA[jp];
                ulonglong2 Bv = shB[jp];
                u64 p = ffma2(nzp, Bv.x, dp);
                p = ffma2(nyp, A.y, p);
                p = ffma2(nxp, A.x, p);
                ptab[jp * 16 + hh] = p;
            }
        }
    }

    // ---- per-thread row constants: rows 4ig..4ig+3 of this i-tile ----
    const int r0 = itile * 64 + ig * 4;
    u64 m2x[4], m2y[4], m2z[4], p4[4][8];
    float ssr[4];
    #pragma unroll
    for (int r = 0; r < 4; ++r) {
        float sx = pb[3 * (r0 + r) + 0];
        float sy = pb[3 * (r0 + r) + 1];
        float sz = pb[3 * (r0 + r) + 2];
        ssr[r] = fmaf(sx, sx, fmaf(sy, sy, sz * sz));
        m2x[r] = pk2(-2.0f * sx, -2.0f * sx);
        m2y[r] = pk2(-2.0f * sy, -2.0f * sy);
        m2z[r] = pk2(-2.0f * sz, -2.0f * sz);
        #pragma unroll
        for (int k = 0; k < 8; ++k) {
            int h = hg * 8 + k;
            float p = fmaf(nh4[h][0], sx, fmaf(nh4[h][1], sy, fmaf(nh4[h][2], sz, nh4[h][3])));
            p4[r][k] = pk2(4.0f * p, 4.0f * p);
        }
    }
    if (t < 16) {                        // ig==t, hg==0, js==0
        #pragma unroll
        for (int r = 0; r < 4; ++r) ssv[t * 4 + r] = ssr[r];
    }
    __syncthreads();

    // ---- mainloop: 64 j-packs, software-pipelined prefetch ----
    const float INF = __int_as_float(0x7f800000);
    float m[4][8];
    #pragma unroll
    for (int r = 0; r < 4; ++r)
        #pragma unroll
        for (int k = 0; k < 8; ++k) m[r][k] = INF;

    const int jbeg = js << 6;
    ulonglong2 A  = shA[jbeg];
    ulonglong2 Bv = shB[jbeg];
    const ulonglong2* pr0 = (const ulonglong2*)&ptab[jbeg * 16 + hg * 8];
    ulonglong2 q0 = pr0[0], q1 = pr0[1], q2 = pr0[2], q3 = pr0[3];

    #pragma unroll 2
    for (int jj = 0; jj < 64; ++jj) {
        const int jpn = jbeg + jj + 1;
        ulonglong2 An = shA[jpn];
        ulonglong2 Bn = shB[jpn];
        const ulonglong2* prn = (const ulonglong2*)&ptab[jpn * 16 + hg * 8];
        ulonglong2 qn0 = prn[0], qn1 = prn[1], qn2 = prn[2], qn3 = prn[3];

        u64 vv[4];
        #pragma unroll
        for (int r = 0; r < 4; ++r) {
            u64 v = ffma2(m2z[r], Bv.x, Bv.y);
            v = ffma2(m2y[r], A.y, v);
            vv[r] = ffma2(m2x[r], A.x, v);
        }
        u64 qa[8];
        qa[0] = q0.x; qa[1] = q0.y; qa[2] = q1.x; qa[3] = q1.y;
        qa[4] = q2.x; qa[5] = q2.y; qa[6] = q3.x; qa[7] = q3.y;
        #pragma unroll
        for (int k = 0; k < 8; ++k) {
            #pragma unroll
            for (int r = 0; r < 4; ++r) {
                float l, h;
                unpk2(ffma2(p4[r][k], qa[k], vv[r]), l, h);
                m[r][k] = fminf(m[r][k], fminf(l, h));
            }
        }
        A = An; Bv = Bn; q0 = qn0; q1 = qn1; q2 = qn2; q3 = qn3;
    }
    __syncthreads();

    // ---- stage 0: publish per-thread mins into dead ptab ----
    float* red = (float*)ptab;           // [8 slices][32 groups][32 vals] = 32KB
    {
        const int grp = ig * 2 + hg;
        float4* d = (float4*)&red[(js * 32 + grp) * 32];
        #pragma unroll
        for (int r = 0; r < 4; ++r) {
            d[r * 2 + 0] = make_float4(m[r][0], m[r][1], m[r][2], m[r][3]);
            d[r * 2 + 1] = make_float4(m[r][4], m[r][5], m[r][6], m[r][7]);
        }
    }
    __syncthreads();

    // ---- stage A: min over 8 slices -> sm2[row][head] ----
    float* sm2 = red + 8192;             // [64][16] floats (4KB)
    {
        const int grp = t >> 3, q = t & 7;
        float4 mv = *(const float4*)&red[(0 * 32 + grp) * 32 + q * 4];
        #pragma unroll
        for (int s = 1; s < 8; ++s) {
            float4 x = *(const float4*)&red[(s * 32 + grp) * 32 + q * 4];
            mv.x = fminf(mv.x, x.x); mv.y = fminf(mv.y, x.y);
            mv.z = fminf(mv.z, x.z); mv.w = fminf(mv.w, x.w);
        }
        const int gi = grp >> 1, hgrp = grp & 1;
        const int row = gi * 4 + (q >> 1);
        const int hb  = hgrp * 8 + (q & 1) * 4;
        *(float4*)&sm2[row * 16 + hb] = mv;
    }
    __syncthreads();

    // ---- stage B: sum (ss_r + min) over 64 rows per head ----
    {
        const int h = t >> 4, c = t & 15;
        float s = 0.f;
        #pragma unroll
        for (int i = 0; i < 4; ++i) {
            const int r = c * 4 + i;
            s += ssv[r] + sm2[r * 16 + h];
        }
        #pragma unroll
        for (int o = 8; o > 0; o >>= 1)
            s += __shfl_down_sync(0xffffffffu, s, o, 16);
        if (c == 0) g_part[bh][h] = s;
    }
}

// One block, 128 threads (proven structure): thread t = (b,h).
// sde assembled deterministically from the 16 i-tile partials.
__global__ void __launch_bounds__(128, 1)
final_kernel(const float* __restrict__ y_pred, float* __restrict__ out)
{
    const int t  = threadIdx.x;
    const int eb = t >> 4;
    const int eh = t & 15;

    __shared__ float hnx[128], hny[128], hnz[128], hsd[128], hkey[128];

    const float* ypp = y_pred + 4 * t;
    float nx = ypp[0], ny = ypp[1], nz = ypp[2], pd = ypp[3];
    float iv = 1.0f / sqrtf(nx * nx + ny * ny + nz * nz);
    nx *= iv; ny *= iv; nz *= iv;

    float acc = 0.0f;
    #pragma unroll
    for (int it = 0; it < 16; ++it) acc += g_part[eb * 16 + it][eh];
    float sde = 2.0f * (acc * (1.0f / 1024.0f));

    hnx[t] = nx; hny[t] = ny; hnz[t] = nz; hsd[t] = sde;
    __syncthreads();

    const int base = eb * H_DIM;
    float mn = hsd[base], mx = hsd[base];
    #pragma unroll
    for (int g2 = 1; g2 < H_DIM; ++g2) {
        mn = fminf(mn, hsd[base + g2]); mx = fmaxf(mx, hsd[base + g2]);
    }
    float conf = 1.0f - (sde - mn) / fabsf(mx - mn);

    // (ang<30 || 180-ang<30)  <=>  |cos| > cos(30deg)  (acos monotone)
    const float COS30 = 0.86602540378443864676f;
    bool valid = (sde <= 10.0f);
    bool any = false;
    #pragma unroll
    for (int g2 = 0; g2 < H_DIM; ++g2) {
        if (g2 == eh) continue;
        float c = nx * hnx[base + g2] + ny * hny[base + g2] + nz * hnz[base + g2];
        c = fminf(1.0f, fmaxf(-1.0f, c));
        if (fabsf(c) > COS30 && (hsd[base + g2] <= 10.0f) && (sde >= hsd[base + g2]))
            any = true;
    }
    bool keep = valid && !any;
    hkey[t] = keep ? conf : __int_as_float(0xff800000);
    __syncthreads();

    float key = hkey[t];
    int rank = 0;
    #pragma unroll
    for (int g2 = 0; g2 < H_DIM; ++g2) {
        float kg = hkey[base + g2];
        if (kg > key || (kg == key && g2 < eh)) rank++;
    }
    float* o = out + (base + rank) * 8;
    if (keep) {
        float cx = g_cm[eb][0], cy = g_cm[eb][1], cz = g_cm[eb][2];
        float pj = fmaf(nx, cx, fmaf(ny, cy, fmaf(nz, cz, pd)));
        o[0] = nx; o[1] = ny; o[2] = nz;
        o[3] = cx - pj * nx;
        o[4] = cy - pj * ny;
        o[5] = cz - pj * nz;
        o[6] = conf;
        o[7] = sde;
    } else {
        #pragma unroll
        for (int c = 0; c < 8; ++c) o[c] = 0.0f;
    }
}

extern "C" void kernel_launch(void* const* d_in, const int* in_sizes, int n_in,
                              void* d_out, int out_size)
{
    const float* y_pred = (const float*)d_in[0];   // (8,16,4)
    const float* sp     = (const float*)d_in[1];   // (8,1024,3)
    float* out          = (float*)d_out;           // (8,16,8)

    chamfer_kernel<<<B_DIM * H_DIM, 256>>>(y_pred, sp);
    final_kernel<<<1, 128>>>(y_pred, out);
}